// round 1
// baseline (speedup 1.0000x reference)
#include <cuda_runtime.h>
#include <cstdint>

#define D_MODEL 4096
#define E3      12288
#define NHEADS  32
#define HDIM    128
#define BATCH   2
#define SEQ     2048
#define ROWS    (BATCH*SEQ)   /* 4096 */
#define CLIP_V  8.0f
#define LN_EPS  1e-5f

// Scratch (allocation-free rule: __device__ globals)
__device__ float g_qkv[(size_t)ROWS * E3];       // [4096][12288] post-GEMM1 (q|k|v)
__device__ float g_attn[(size_t)ROWS * D_MODEL]; // [4096][4096]  attention output

// ---------------------------------------------------------------------------
// GEMM: C[m][n] = sum_k A[m][k] * W[n][k]   (both operands K-contiguous)
// 64x64 block tile, BK=16, 256 threads, 4x4 register tile per thread.
// ---------------------------------------------------------------------------
template<bool DO_CLIP>
__global__ __launch_bounds__(256)
void gemm_nt(const float* __restrict__ A, const float* __restrict__ W,
             float* __restrict__ C, int M, int N, int K) {
    __shared__ float As[64][17];
    __shared__ float Bs[64][17];
    const int tid = threadIdx.x;
    const int tx = tid & 15, ty = tid >> 4;
    const int m0 = blockIdx.y << 6, n0 = blockIdx.x << 6;

    const int lrow = tid >> 2;          // 0..63
    const int lcol = (tid & 3) << 2;    // 0,4,8,12
    const float* Ap = A + (size_t)(m0 + lrow) * K + lcol;
    const float* Wp = W + (size_t)(n0 + lrow) * K + lcol;

    float acc[4][4] = {};
    for (int k0 = 0; k0 < K; k0 += 16) {
        float4 av = *(const float4*)(Ap + k0);
        float4 wv = *(const float4*)(Wp + k0);
        As[lrow][lcol]   = av.x; As[lrow][lcol+1] = av.y;
        As[lrow][lcol+2] = av.z; As[lrow][lcol+3] = av.w;
        Bs[lrow][lcol]   = wv.x; Bs[lrow][lcol+1] = wv.y;
        Bs[lrow][lcol+2] = wv.z; Bs[lrow][lcol+3] = wv.w;
        __syncthreads();
#pragma unroll
        for (int kk = 0; kk < 16; kk++) {
            float a[4], b[4];
#pragma unroll
            for (int i = 0; i < 4; i++) a[i] = As[ty*4+i][kk];
#pragma unroll
            for (int j = 0; j < 4; j++) b[j] = Bs[tx*4+j][kk];
#pragma unroll
            for (int i = 0; i < 4; i++)
#pragma unroll
                for (int j = 0; j < 4; j++)
                    acc[i][j] = fmaf(a[i], b[j], acc[i][j]);
        }
        __syncthreads();
    }
#pragma unroll
    for (int i = 0; i < 4; i++) {
        float* cp = C + (size_t)(m0 + ty*4 + i) * N + n0 + tx*4;
#pragma unroll
        for (int j = 0; j < 4; j++) {
            float v = acc[i][j];
            if (DO_CLIP) v = fminf(fmaxf(v, -CLIP_V), CLIP_V);
            cp[j] = v;
        }
    }
}

// ---------------------------------------------------------------------------
// LayerNorm over D_MODEL, in place on a column-slice of g_qkv.
// One block per row. Population variance (matches jnp.var).
// ---------------------------------------------------------------------------
__global__ __launch_bounds__(256)
void ln_kernel(float* __restrict__ base, int col_off,
               const float* __restrict__ w, const float* __restrict__ b) {
    __shared__ float red0[8], red1[8];
    __shared__ float mu_s, inv_s;
    float* x = base + (size_t)blockIdx.x * E3 + col_off;
    const int tid = threadIdx.x;

    float s = 0.f, s2 = 0.f;
    for (int i = tid; i < D_MODEL; i += 256) {
        float v = x[i]; s += v; s2 += v * v;
    }
#pragma unroll
    for (int o = 16; o; o >>= 1) {
        s  += __shfl_down_sync(0xffffffffu, s,  o);
        s2 += __shfl_down_sync(0xffffffffu, s2, o);
    }
    if ((tid & 31) == 0) { red0[tid >> 5] = s; red1[tid >> 5] = s2; }
    __syncthreads();
    if (tid == 0) {
        float S = 0.f, S2 = 0.f;
#pragma unroll
        for (int i = 0; i < 8; i++) { S += red0[i]; S2 += red1[i]; }
        float mu = S * (1.f / D_MODEL);
        float var = S2 * (1.f / D_MODEL) - mu * mu;
        mu_s = mu;
        inv_s = rsqrtf(var + LN_EPS);
    }
    __syncthreads();
    const float mu = mu_s, inv = inv_s;
    for (int i = tid; i < D_MODEL; i += 256) {
        x[i] = (x[i] - mu) * inv * w[i] + b[i];
    }
}

// ---------------------------------------------------------------------------
// Flash attention (fp32, causal, ALiBi). grid = (S/64, H, B), 256 threads.
// Q tile 64x128 (pre-scaled), KV tiles 64x128, online softmax.
// Thread (tx,ty) in 16x16: S-tile 4x4 (rows ty*4+i, cols tx*4+j),
// O accumulator 4x8 (rows ty*4+i, cols tx*8+c).
// ---------------------------------------------------------------------------
__global__ __launch_bounds__(256)
void attn_kernel(const float* __restrict__ qkv, float* __restrict__ outp) {
    extern __shared__ float sm[];
    float* Qs   = sm;                 // 64*128
    float* Ks   = Qs + 64*128;        // 64*129 (padded)
    float* Vs   = Ks + 64*129;        // 64*128
    float* Ps   = Vs + 64*128;        // 64*68  (padded)
    float* rowm = Ps + 64*68;         // 64
    float* rowl = rowm + 64;          // 64
    float* rowr = rowl + 64;          // 64

    const int qt = blockIdx.x, h = blockIdx.y, b = blockIdx.z;
    const int tid = threadIdx.x;
    const int tx = tid & 15, ty = tid >> 4;
    const float scale = 0.08838834764831845f;            // 1/sqrt(128)
    const float slope = exp2f(-0.25f * (float)(h + 1));  // ALiBi, H == next_p2
    const size_t rowbase = (size_t)b * SEQ;

    // Load + pre-scale Q tile
    for (int i = tid; i < 64 * HDIM / 4; i += 256) {
        int r = i >> 5; int c = (i & 31) << 2;
        float4 v = *(const float4*)(qkv + (rowbase + qt*64 + r) * E3 + h*HDIM + c);
        float* q = Qs + r*HDIM + c;
        q[0] = v.x * scale; q[1] = v.y * scale; q[2] = v.z * scale; q[3] = v.w * scale;
    }
    if (tid < 64) { rowm[tid] = -1e30f; rowl[tid] = 0.f; }
    float o[4][8];
#pragma unroll
    for (int i = 0; i < 4; i++)
#pragma unroll
        for (int c = 0; c < 8; c++) o[i][c] = 0.f;
    __syncthreads();

    for (int kt = 0; kt <= qt; kt++) {
        // Load K (padded) and V tiles
        for (int i = tid; i < 64 * HDIM / 4; i += 256) {
            int r = i >> 5; int c = (i & 31) << 2;
            const float* kp = qkv + (rowbase + kt*64 + r) * E3 + D_MODEL + h*HDIM + c;
            float4 kv = *(const float4*)kp;
            float* kd = Ks + r*129 + c;
            kd[0] = kv.x; kd[1] = kv.y; kd[2] = kv.z; kd[3] = kv.w;
            float4 vv = *(const float4*)(kp + D_MODEL);
            *(float4*)(Vs + r*HDIM + c) = vv;
        }
        __syncthreads();

        // S = (Q*scale) K^T
        float sacc[4][4] = {};
#pragma unroll 4
        for (int kk = 0; kk < HDIM; kk++) {
            float a[4], bb[4];
#pragma unroll
            for (int i = 0; i < 4; i++) a[i]  = Qs[(ty*4+i)*HDIM + kk];
#pragma unroll
            for (int j = 0; j < 4; j++) bb[j] = Ks[(tx*4+j)*129 + kk];
#pragma unroll
            for (int i = 0; i < 4; i++)
#pragma unroll
                for (int j = 0; j < 4; j++)
                    sacc[i][j] = fmaf(a[i], bb[j], sacc[i][j]);
        }

        // ALiBi + causal mask -> Ps
        const int qb = qt*64 + ty*4, kb = kt*64 + tx*4;
#pragma unroll
        for (int i = 0; i < 4; i++)
#pragma unroll
            for (int j = 0; j < 4; j++) {
                int qi = qb + i, kj = kb + j;
                float v = sacc[i][j] + slope * (float)(kj - qi);
                if (kj > qi) v = -1e30f;
                Ps[(ty*4+i)*68 + tx*4+j] = v;
            }
        __syncthreads();

        // Online softmax (one thread per row)
        if (tid < 64) {
            float* prow = Ps + tid*68;
            float m_old = rowm[tid];
            float mx = m_old;
#pragma unroll 8
            for (int j = 0; j < 64; j++) mx = fmaxf(mx, prow[j]);
            float r_ = __expf(m_old - mx);
            float sum = 0.f;
#pragma unroll 8
            for (int j = 0; j < 64; j++) {
                float p = __expf(prow[j] - mx);
                prow[j] = p; sum += p;
            }
            rowm[tid] = mx;
            rowl[tid] = rowl[tid] * r_ + sum;
            rowr[tid] = r_;
        }
        __syncthreads();

        // Rescale O, accumulate P@V
        float rr[4];
#pragma unroll
        for (int i = 0; i < 4; i++) rr[i] = rowr[ty*4+i];
#pragma unroll
        for (int i = 0; i < 4; i++)
#pragma unroll
            for (int c = 0; c < 8; c++) o[i][c] *= rr[i];
#pragma unroll 2
        for (int kk = 0; kk < 64; kk++) {
            float p[4];
#pragma unroll
            for (int i = 0; i < 4; i++) p[i] = Ps[(ty*4+i)*68 + kk];
            float4 v0 = *(const float4*)(Vs + kk*HDIM + tx*8);
            float4 v1 = *(const float4*)(Vs + kk*HDIM + tx*8 + 4);
#pragma unroll
            for (int i = 0; i < 4; i++) {
                o[i][0] = fmaf(p[i], v0.x, o[i][0]);
                o[i][1] = fmaf(p[i], v0.y, o[i][1]);
                o[i][2] = fmaf(p[i], v0.z, o[i][2]);
                o[i][3] = fmaf(p[i], v0.w, o[i][3]);
                o[i][4] = fmaf(p[i], v1.x, o[i][4]);
                o[i][5] = fmaf(p[i], v1.y, o[i][5]);
                o[i][6] = fmaf(p[i], v1.z, o[i][6]);
                o[i][7] = fmaf(p[i], v1.w, o[i][7]);
            }
        }
        __syncthreads();
    }

    // Normalize and write
#pragma unroll
    for (int i = 0; i < 4; i++) {
        float inv = 1.f / rowl[ty*4+i];
        float* op = outp + (rowbase + qt*64 + ty*4 + i) * (size_t)D_MODEL + h*HDIM + tx*8;
        float4 w0 = make_float4(o[i][0]*inv, o[i][1]*inv, o[i][2]*inv, o[i][3]*inv);
        float4 w1 = make_float4(o[i][4]*inv, o[i][5]*inv, o[i][6]*inv, o[i][7]*inv);
        *(float4*)op = w0;
        *(float4*)(op + 4) = w1;
    }
}

// ---------------------------------------------------------------------------
extern "C" void kernel_launch(void* const* d_in, const int* in_sizes, int n_in,
                              void* d_out, int out_size) {
    const float* hidden = (const float*)d_in[0];
    const float* w_qkv  = (const float*)d_in[1];
    const float* q_ln_w = (const float*)d_in[2];
    const float* q_ln_b = (const float*)d_in[3];
    const float* k_ln_w = (const float*)d_in[4];
    const float* k_ln_b = (const float*)d_in[5];
    const float* w_out  = (const float*)d_in[6];
    float* out = (float*)d_out;

    float *qkv, *attn;
    cudaGetSymbolAddress((void**)&qkv, g_qkv);
    cudaGetSymbolAddress((void**)&attn, g_attn);

    // 1) QKV projection + clip
    dim3 g1(E3 / 64, ROWS / 64);
    gemm_nt<true><<<g1, 256>>>(hidden, w_qkv, qkv, ROWS, E3, D_MODEL);

    // 2) q/k LayerNorms (full d_model)
    ln_kernel<<<ROWS, 256>>>(qkv, 0,       q_ln_w, q_ln_b);
    ln_kernel<<<ROWS, 256>>>(qkv, D_MODEL, k_ln_w, k_ln_b);

    // 3) Flash attention
    int smem = (64*128 + 64*129 + 64*128 + 64*68 + 3*64) * (int)sizeof(float);
    cudaFuncSetAttribute(attn_kernel, cudaFuncAttributeMaxDynamicSharedMemorySize, smem);
    dim3 ga(SEQ / 64, NHEADS, BATCH);
    attn_kernel<<<ga, 256, smem>>>(qkv, attn);

    // 4) Output projection -> d_out
    dim3 g2(D_MODEL / 64, ROWS / 64);
    gemm_nt<false><<<g2, 256>>>(attn, w_out, out, ROWS, D_MODEL, D_MODEL);
}

// round 3
// speedup vs baseline: 2.0018x; 2.0018x over previous
#include <cuda_runtime.h>
#include <cstdint>

#define D_MODEL 4096
#define E3      12288
#define NHEADS  32
#define HDIM    128
#define BATCH   2
#define SEQ     2048
#define ROWS    (BATCH*SEQ)   /* 4096 */
#define CLIP_V  8.0f
#define LN_EPS  1e-5f

// Scratch (allocation-free rule: __device__ globals)
__device__ float g_qkv[(size_t)ROWS * E3];       // [4096][12288] post-GEMM1 (q|k|v)
__device__ float g_attn[(size_t)ROWS * D_MODEL]; // [4096][4096]  attention output

// ===========================================================================
// mma.sync tf32 helpers (sm_80+ — no arch-specific suffix required)
// ===========================================================================
__device__ __forceinline__ uint32_t f2tf(float f) {
    uint32_t r;
    asm("cvt.rna.tf32.f32 %0, %1;" : "=r"(r) : "f"(f));
    return r;
}

__device__ __forceinline__ void mma_tf32(float* d, const uint32_t* a, const uint32_t* b) {
    asm volatile(
        "mma.sync.aligned.m16n8k8.row.col.f32.tf32.tf32.f32 "
        "{%0,%1,%2,%3}, {%4,%5,%6,%7}, {%8,%9}, {%0,%1,%2,%3};"
        : "+f"(d[0]), "+f"(d[1]), "+f"(d[2]), "+f"(d[3])
        : "r"(a[0]), "r"(a[1]), "r"(a[2]), "r"(a[3]), "r"(b[0]), "r"(b[1]));
}

// ===========================================================================
// TF32 tensor-core GEMM: C[m][n] = sum_k A[m][k] * W[n][k]
// CTA 128x128, BK=32, 8 warps (2m x 4n), warp tile 64x32.
// Double-buffered smem (padded stride 36), register prefetch.
// grid = (Ntot/128, M/128), 256 threads.
// ===========================================================================
#define BM 128
#define BN 128
#define BK 32
#define LDP 36            // padded row stride (floats)
#define TILE_U32 (128*LDP)
#define GEMM_SMEM (4 * TILE_U32 * 4)   /* A0 B0 A1 B1, 73728 B */

template<bool DO_CLIP>
__global__ __launch_bounds__(256)
void gemm_mma(const float* __restrict__ A, const float* __restrict__ W,
              float* __restrict__ C, int Ntot, int K) {
    extern __shared__ uint32_t sm[];
    uint32_t* As[2] = { sm,                sm + 2 * TILE_U32 };
    uint32_t* Bs[2] = { sm + TILE_U32,     sm + 3 * TILE_U32 };

    const int tid  = threadIdx.x;
    const int lane = tid & 31;
    const int warp = tid >> 5;
    const int wm0  = (warp >> 2) << 6;   // 0 or 64
    const int wn0  = (warp & 3) << 5;    // 0,32,64,96
    const int m0 = blockIdx.y << 7, n0 = blockIdx.x << 7;

    const float* Ab = A + (size_t)m0 * K;
    const float* Wb = W + (size_t)n0 * K;

    // LDG mapping: idx = tid + i*256 over 1024 float4 slots; row = idx>>3, cg = idx&7
    const int lrow = tid >> 3;          // base row for i=0 (rows advance by 32 per i)
    const int lcg  = tid & 7;

    float acc[4][4][4];
#pragma unroll
    for (int a = 0; a < 4; a++)
#pragma unroll
        for (int b = 0; b < 4; b++)
#pragma unroll
            for (int c = 0; c < 4; c++) acc[a][b][c] = 0.f;

    const int NS = K >> 5;              // 32-wide K stages
    float4 pa[4], pb[4];

    // prefetch stage 0 into registers
#pragma unroll
    for (int i = 0; i < 4; i++) {
        int row = lrow + (i << 5);
        pa[i] = *(const float4*)(Ab + (size_t)row * K + lcg * 4);
        pb[i] = *(const float4*)(Wb + (size_t)row * K + lcg * 4);
    }
    // store stage 0 (with RNA tf32 rounding)
#pragma unroll
    for (int i = 0; i < 4; i++) {
        int row = lrow + (i << 5);
        uint32_t* pda = As[0] + row * LDP + lcg * 4;
        pda[0] = f2tf(pa[i].x); pda[1] = f2tf(pa[i].y);
        pda[2] = f2tf(pa[i].z); pda[3] = f2tf(pa[i].w);
        uint32_t* pdb = Bs[0] + row * LDP + lcg * 4;
        pdb[0] = f2tf(pb[i].x); pdb[1] = f2tf(pb[i].y);
        pdb[2] = f2tf(pb[i].z); pdb[3] = f2tf(pb[i].w);
    }
    __syncthreads();

    for (int s = 0; s < NS; s++) {
        // prefetch next stage
        if (s + 1 < NS) {
            const int k0 = (s + 1) << 5;
#pragma unroll
            for (int i = 0; i < 4; i++) {
                int row = lrow + (i << 5);
                pa[i] = *(const float4*)(Ab + (size_t)row * K + k0 + lcg * 4);
                pb[i] = *(const float4*)(Wb + (size_t)row * K + k0 + lcg * 4);
            }
        }

        // compute current stage
        const uint32_t* Ac = As[s & 1];
        const uint32_t* Bc = Bs[s & 1];
#pragma unroll
        for (int kk = 0; kk < 4; kk++) {
            const int kb = kk << 3;
            uint32_t af[4][4], bf[4][2];
#pragma unroll
            for (int mt = 0; mt < 4; mt++) {
                int r = wm0 + (mt << 4) + (lane >> 2);
                int c = kb + (lane & 3);
                af[mt][0] = Ac[r * LDP + c];
                af[mt][1] = Ac[(r + 8) * LDP + c];
                af[mt][2] = Ac[r * LDP + c + 4];
                af[mt][3] = Ac[(r + 8) * LDP + c + 4];
            }
#pragma unroll
            for (int nt = 0; nt < 4; nt++) {
                int n = wn0 + (nt << 3) + (lane >> 2);
                int c = kb + (lane & 3);
                bf[nt][0] = Bc[n * LDP + c];
                bf[nt][1] = Bc[n * LDP + c + 4];
            }
#pragma unroll
            for (int mt = 0; mt < 4; mt++)
#pragma unroll
                for (int nt = 0; nt < 4; nt++)
                    mma_tf32(acc[mt][nt], af[mt], bf[nt]);
        }

        // store next stage into the other buffer
        if (s + 1 < NS) {
            uint32_t* Ad = As[(s + 1) & 1];
            uint32_t* Bd = Bs[(s + 1) & 1];
#pragma unroll
            for (int i = 0; i < 4; i++) {
                int row = lrow + (i << 5);
                uint32_t* pda = Ad + row * LDP + lcg * 4;
                pda[0] = f2tf(pa[i].x); pda[1] = f2tf(pa[i].y);
                pda[2] = f2tf(pa[i].z); pda[3] = f2tf(pa[i].w);
                uint32_t* pdb = Bd + row * LDP + lcg * 4;
                pdb[0] = f2tf(pb[i].x); pdb[1] = f2tf(pb[i].y);
                pdb[2] = f2tf(pb[i].z); pdb[3] = f2tf(pb[i].w);
            }
            __syncthreads();
        }
    }

    // epilogue: fragment layout -> global, float2 stores, optional clip
#pragma unroll
    for (int mt = 0; mt < 4; mt++) {
#pragma unroll
        for (int nt = 0; nt < 4; nt++) {
            int row = m0 + wm0 + (mt << 4) + (lane >> 2);
            int col = n0 + wn0 + (nt << 3) + ((lane & 3) << 1);
            float2 v0 = make_float2(acc[mt][nt][0], acc[mt][nt][1]);
            float2 v1 = make_float2(acc[mt][nt][2], acc[mt][nt][3]);
            if (DO_CLIP) {
                v0.x = fminf(fmaxf(v0.x, -CLIP_V), CLIP_V);
                v0.y = fminf(fmaxf(v0.y, -CLIP_V), CLIP_V);
                v1.x = fminf(fmaxf(v1.x, -CLIP_V), CLIP_V);
                v1.y = fminf(fmaxf(v1.y, -CLIP_V), CLIP_V);
            }
            *(float2*)(C + (size_t)row * Ntot + col) = v0;
            *(float2*)(C + (size_t)(row + 8) * Ntot + col) = v1;
        }
    }
}

// ---------------------------------------------------------------------------
// LayerNorm over D_MODEL, in place on a column-slice of g_qkv.
// ---------------------------------------------------------------------------
__global__ __launch_bounds__(256)
void ln_kernel(float* __restrict__ base, int col_off,
               const float* __restrict__ w, const float* __restrict__ b) {
    __shared__ float red0[8], red1[8];
    __shared__ float mu_s, inv_s;
    float* x = base + (size_t)blockIdx.x * E3 + col_off;
    const int tid = threadIdx.x;

    float s = 0.f, s2 = 0.f;
    for (int i = tid; i < D_MODEL; i += 256) {
        float v = x[i]; s += v; s2 += v * v;
    }
#pragma unroll
    for (int o = 16; o; o >>= 1) {
        s  += __shfl_down_sync(0xffffffffu, s,  o);
        s2 += __shfl_down_sync(0xffffffffu, s2, o);
    }
    if ((tid & 31) == 0) { red0[tid >> 5] = s; red1[tid >> 5] = s2; }
    __syncthreads();
    if (tid == 0) {
        float S = 0.f, S2 = 0.f;
#pragma unroll
        for (int i = 0; i < 8; i++) { S += red0[i]; S2 += red1[i]; }
        float mu = S * (1.f / D_MODEL);
        float var = S2 * (1.f / D_MODEL) - mu * mu;
        mu_s = mu;
        inv_s = rsqrtf(var + LN_EPS);
    }
    __syncthreads();
    const float mu = mu_s, inv = inv_s;
    for (int i = tid; i < D_MODEL; i += 256) {
        x[i] = (x[i] - mu) * inv * w[i] + b[i];
    }
}

// ---------------------------------------------------------------------------
// Flash attention (fp32, causal, ALiBi) — unchanged (known correct).
// ---------------------------------------------------------------------------
__global__ __launch_bounds__(256)
void attn_kernel(const float* __restrict__ qkv, float* __restrict__ outp) {
    extern __shared__ float smf[];
    float* Qs   = smf;                // 64*128
    float* Ks   = Qs + 64*128;        // 64*129 (padded)
    float* Vs   = Ks + 64*129;        // 64*128
    float* Ps   = Vs + 64*128;        // 64*68  (padded)
    float* rowm = Ps + 64*68;         // 64
    float* rowl = rowm + 64;          // 64
    float* rowr = rowl + 64;          // 64

    const int qt = blockIdx.x, h = blockIdx.y, b = blockIdx.z;
    const int tid = threadIdx.x;
    const int tx = tid & 15, ty = tid >> 4;
    const float scale = 0.08838834764831845f;            // 1/sqrt(128)
    const float slope = exp2f(-0.25f * (float)(h + 1));  // ALiBi, H == next_p2
    const size_t rowbase = (size_t)b * SEQ;

    for (int i = tid; i < 64 * HDIM / 4; i += 256) {
        int r = i >> 5; int c = (i & 31) << 2;
        float4 v = *(const float4*)(qkv + (rowbase + qt*64 + r) * E3 + h*HDIM + c);
        float* q = Qs + r*HDIM + c;
        q[0] = v.x * scale; q[1] = v.y * scale; q[2] = v.z * scale; q[3] = v.w * scale;
    }
    if (tid < 64) { rowm[tid] = -1e30f; rowl[tid] = 0.f; }
    float o[4][8];
#pragma unroll
    for (int i = 0; i < 4; i++)
#pragma unroll
        for (int c = 0; c < 8; c++) o[i][c] = 0.f;
    __syncthreads();

    for (int kt = 0; kt <= qt; kt++) {
        for (int i = tid; i < 64 * HDIM / 4; i += 256) {
            int r = i >> 5; int c = (i & 31) << 2;
            const float* kp = qkv + (rowbase + kt*64 + r) * E3 + D_MODEL + h*HDIM + c;
            float4 kv = *(const float4*)kp;
            float* kd = Ks + r*129 + c;
            kd[0] = kv.x; kd[1] = kv.y; kd[2] = kv.z; kd[3] = kv.w;
            float4 vv = *(const float4*)(kp + D_MODEL);
            *(float4*)(Vs + r*HDIM + c) = vv;
        }
        __syncthreads();

        float sacc[4][4] = {};
#pragma unroll 4
        for (int kk = 0; kk < HDIM; kk++) {
            float a[4], bb[4];
#pragma unroll
            for (int i = 0; i < 4; i++) a[i]  = Qs[(ty*4+i)*HDIM + kk];
#pragma unroll
            for (int j = 0; j < 4; j++) bb[j] = Ks[(tx*4+j)*129 + kk];
#pragma unroll
            for (int i = 0; i < 4; i++)
#pragma unroll
                for (int j = 0; j < 4; j++)
                    sacc[i][j] = fmaf(a[i], bb[j], sacc[i][j]);
        }

        const int qb = qt*64 + ty*4, kb = kt*64 + tx*4;
#pragma unroll
        for (int i = 0; i < 4; i++)
#pragma unroll
            for (int j = 0; j < 4; j++) {
                int qi = qb + i, kj = kb + j;
                float v = sacc[i][j] + slope * (float)(kj - qi);
                if (kj > qi) v = -1e30f;
                Ps[(ty*4+i)*68 + tx*4+j] = v;
            }
        __syncthreads();

        if (tid < 64) {
            float* prow = Ps + tid*68;
            float m_old = rowm[tid];
            float mx = m_old;
#pragma unroll 8
            for (int j = 0; j < 64; j++) mx = fmaxf(mx, prow[j]);
            float r_ = __expf(m_old - mx);
            float sum = 0.f;
#pragma unroll 8
            for (int j = 0; j < 64; j++) {
                float p = __expf(prow[j] - mx);
                prow[j] = p; sum += p;
            }
            rowm[tid] = mx;
            rowl[tid] = rowl[tid] * r_ + sum;
            rowr[tid] = r_;
        }
        __syncthreads();

        float rr[4];
#pragma unroll
        for (int i = 0; i < 4; i++) rr[i] = rowr[ty*4+i];
#pragma unroll
        for (int i = 0; i < 4; i++)
#pragma unroll
            for (int c = 0; c < 8; c++) o[i][c] *= rr[i];
#pragma unroll 2
        for (int kk = 0; kk < 64; kk++) {
            float p[4];
#pragma unroll
            for (int i = 0; i < 4; i++) p[i] = Ps[(ty*4+i)*68 + kk];
            float4 v0 = *(const float4*)(Vs + kk*HDIM + tx*8);
            float4 v1 = *(const float4*)(Vs + kk*HDIM + tx*8 + 4);
#pragma unroll
            for (int i = 0; i < 4; i++) {
                o[i][0] = fmaf(p[i], v0.x, o[i][0]);
                o[i][1] = fmaf(p[i], v0.y, o[i][1]);
                o[i][2] = fmaf(p[i], v0.z, o[i][2]);
                o[i][3] = fmaf(p[i], v0.w, o[i][3]);
                o[i][4] = fmaf(p[i], v1.x, o[i][4]);
                o[i][5] = fmaf(p[i], v1.y, o[i][5]);
                o[i][6] = fmaf(p[i], v1.z, o[i][6]);
                o[i][7] = fmaf(p[i], v1.w, o[i][7]);
            }
        }
        __syncthreads();
    }

#pragma unroll
    for (int i = 0; i < 4; i++) {
        float inv = 1.f / rowl[ty*4+i];
        float* op = outp + (rowbase + qt*64 + ty*4 + i) * (size_t)D_MODEL + h*HDIM + tx*8;
        float4 w0 = make_float4(o[i][0]*inv, o[i][1]*inv, o[i][2]*inv, o[i][3]*inv);
        float4 w1 = make_float4(o[i][4]*inv, o[i][5]*inv, o[i][6]*inv, o[i][7]*inv);
        *(float4*)op = w0;
        *(float4*)(op + 4) = w1;
    }
}

// ---------------------------------------------------------------------------
extern "C" void kernel_launch(void* const* d_in, const int* in_sizes, int n_in,
                              void* d_out, int out_size) {
    const float* hidden = (const float*)d_in[0];
    const float* w_qkv  = (const float*)d_in[1];
    const float* q_ln_w = (const float*)d_in[2];
    const float* q_ln_b = (const float*)d_in[3];
    const float* k_ln_w = (const float*)d_in[4];
    const float* k_ln_b = (const float*)d_in[5];
    const float* w_out  = (const float*)d_in[6];
    float* out = (float*)d_out;

    float *qkv, *attn;
    cudaGetSymbolAddress((void**)&qkv, g_qkv);
    cudaGetSymbolAddress((void**)&attn, g_attn);

    cudaFuncSetAttribute(gemm_mma<true>,  cudaFuncAttributeMaxDynamicSharedMemorySize, GEMM_SMEM);
    cudaFuncSetAttribute(gemm_mma<false>, cudaFuncAttributeMaxDynamicSharedMemorySize, GEMM_SMEM);

    // 1) QKV projection + clip (tf32 tensor cores)
    dim3 g1(E3 / 128, ROWS / 128);
    gemm_mma<true><<<g1, 256, GEMM_SMEM>>>(hidden, w_qkv, qkv, E3, D_MODEL);

    // 2) q/k LayerNorms
    ln_kernel<<<ROWS, 256>>>(qkv, 0,       q_ln_w, q_ln_b);
    ln_kernel<<<ROWS, 256>>>(qkv, D_MODEL, k_ln_w, k_ln_b);

    // 3) Flash attention
    int smem = (64*128 + 64*129 + 64*128 + 64*68 + 3*64) * (int)sizeof(float);
    cudaFuncSetAttribute(attn_kernel, cudaFuncAttributeMaxDynamicSharedMemorySize, smem);
    dim3 ga(SEQ / 64, NHEADS, BATCH);
    attn_kernel<<<ga, 256, smem>>>(qkv, attn);

    // 4) Output projection -> d_out (tf32 tensor cores)
    dim3 g2(D_MODEL / 128, ROWS / 128);
    gemm_mma<false><<<g2, 256, GEMM_SMEM>>>(attn, w_out, out, D_MODEL, D_MODEL);
}